// round 7
// baseline (speedup 1.0000x reference)
#include <cuda_runtime.h>
#include <cstdint>

// LoopyBeliefPropagation: B=8, S=128, MAX_ITER=3
//
// Algebra (d = m1 - m0, m normalized over q): d2[j,k] = db2[k] - db1[k]
// (softplus(s_sib) cancels between iterations), so per (i,b) slab the only
// O(S^2) work is C[k] = sum_{k'} v_{k'} softplus(s_sib[b,k,i,k']) plus a
// scalar epilogue. softplus = EX2 + degree-6 poly in z=2e^{-|x|}-1, evaluated
// pairwise with packed fma.rn.f32x2 (R6).
//
// R7: (1) balanced scheduling — pre-kernel compacts heavy slabs (valid i)
// into g_heavy via block prefix-sum; main grid 1024 gives CTAs 0..M-1 the
// heavy slabs (even ~5/SM round-robin) and the rest zero-fill trivial
// columns. (2) software-pipelined double-buffered row loads so DRAM requests
// stay outstanding through each group's compute+reduce.

#define S_DIM 128
#define NSLAB (8 * S_DIM)
#define LN2F 0.69314718055994530942f
#define NL2E 1.4426950408889634f   // log2(e)

__device__ unsigned int g_heavy[NSLAB];
__device__ unsigned int g_trivial[NSLAB];
__device__ unsigned int g_M;
__device__ unsigned int g_okA;

// ---- packed f32x2 helpers ----
__device__ __forceinline__ uint64_t pk2(float lo, float hi) {
    uint64_t r;
    asm("mov.b64 %0, {%1, %2};" : "=l"(r) : "f"(lo), "f"(hi));
    return r;
}
__device__ __forceinline__ uint64_t fma2(uint64_t a, uint64_t b, uint64_t c) {
    uint64_t d;
    asm("fma.rn.f32x2 %0, %1, %2, %3;" : "=l"(d) : "l"(a), "l"(b), "l"(c));
    return d;
}
__device__ __forceinline__ uint64_t add2(uint64_t a, uint64_t b) {
    uint64_t d;
    asm("add.rn.f32x2 %0, %1, %2;" : "=l"(d) : "l"(a), "l"(b));
    return d;
}
__device__ __forceinline__ float red2(uint64_t a) {
    float lo, hi;
    asm("mov.b64 {%0, %1}, %2;" : "=f"(lo), "=f"(hi) : "l"(a));
    return lo + hi;
}
__device__ __forceinline__ float ex2f(float x) {
    float y;
    asm("ex2.approx.f32 %0, %1;" : "=f"(y) : "f"(x));
    return y;
}

// Polynomial coefficients for g(z) ~= log1p(e), z = 2e-1 in [-1,1]
#define PB0  0.40545900f
#define PB1  0.33334200f
#define PB2 -0.05556080f
#define PB3  0.01227890f
#define PB4 -0.00305808f
#define PB5  0.00095157f
#define PB6 -0.00027211f

__device__ __forceinline__ uint64_t sp2_acc(float x0, float x1,
                                            uint64_t vk2, uint64_t acc) {
    float e0 = ex2f(fmaf(fabsf(x0), -NL2E, 1.0f));   // 2*exp(-|x0|)
    float e1 = ex2f(fmaf(fabsf(x1), -NL2E, 1.0f));
    uint64_t z = add2(pk2(e0, e1), pk2(-1.0f, -1.0f));
    uint64_t g = pk2(PB6, PB6);
    g = fma2(g, z, pk2(PB5, PB5));
    g = fma2(g, z, pk2(PB4, PB4));
    g = fma2(g, z, pk2(PB3, PB3));
    g = fma2(g, z, pk2(PB2, PB2));
    g = fma2(g, z, pk2(PB1, PB1));
    g = fma2(g, z, pk2(PB0, PB0));
    uint64_t sp = add2(pk2(fmaxf(x0, 0.0f), fmaxf(x1, 0.0f)), g);
    return fma2(vk2, sp, acc);
}

__device__ __forceinline__ float softplus_poly(float x) {
    float z = ex2f(fmaf(fabsf(x), -NL2E, 1.0f)) - 1.0f;
    float g = PB6;
    g = fmaf(g, z, PB5);
    g = fmaf(g, z, PB4);
    g = fmaf(g, z, PB3);
    g = fmaf(g, z, PB2);
    g = fmaf(g, z, PB1);
    g = fmaf(g, z, PB0);
    return fmaxf(x, 0.0f) + g;
}

// ---------------------------------------------------------------------------
// Pre-kernel: mask-width detection + heavy/trivial slab compaction.
// ---------------------------------------------------------------------------
__global__ __launch_bounds__(NSLAB)
void schedule_kernel(const unsigned char* __restrict__ mask_raw) {
    __shared__ int sc[NSLAB];
    const int t = threadIdx.x;               // one thread per slab
    const unsigned int* mask_w = reinterpret_cast<const unsigned int*>(mask_raw);

    // Mask element-width detection on batch-0 diagonal (v[0]=0, v[1]=1,
    // monotone non-increasing). R2 evidence: 4-byte elements; keep robust.
    int predA = 1;
    if (t < S_DIM) {
        unsigned char vj  = mask_raw[t * (S_DIM + 1)] != 0;
        unsigned char vj1 = (t < S_DIM - 1)
                          ? (mask_raw[(t + 1) * (S_DIM + 1)] != 0) : 0;
        if (t == 0)              predA = (vj == 0);
        else if (t == 1)         predA = (vj == 1) && (vj >= vj1);
        else if (t < S_DIM - 1)  predA = (vj >= vj1);
    }
    const int okA = __syncthreads_and(predA);
    if (t == 0) g_okA = okA;

    const int bb = t >> 7, i = t & (S_DIM - 1);
    const size_t e = (size_t)(bb * S_DIM + i) * S_DIM + i;
    const int heavy = okA ? (mask_raw[e] != 0) : (mask_w[e] != 0);

    // Hillis-Steele inclusive prefix sum over 1024 flags.
    sc[t] = heavy;
    __syncthreads();
    #pragma unroll
    for (int off = 1; off < NSLAB; off <<= 1) {
        int v   = sc[t];
        int add = (t >= off) ? sc[t - off] : 0;
        __syncthreads();
        sc[t] = v + add;
        __syncthreads();
    }
    const int incl = sc[t];
    const int excl = incl - heavy;
    if (heavy) g_heavy[excl] = t;
    else       g_trivial[t - excl] = t;
    if (t == NSLAB - 1) g_M = incl;
}

// ---------------------------------------------------------------------------
// Main kernel: heavy CTAs compute, trivial CTAs zero-fill.
// ---------------------------------------------------------------------------
__global__ __launch_bounds__(128, 7)
void lbp_kernel(const float* __restrict__ s_edge,
                const float* __restrict__ s_sib,
                const unsigned char* __restrict__ mask_raw,
                float* __restrict__ out)
{
    __shared__ float sm_v[S_DIM];
    __shared__ float sm_pe0[S_DIM];
    __shared__ float sm_pe1[S_DIM];
    __shared__ float sm_C[S_DIM];
    __shared__ float sm_pT[4], sm_pN[4], sm_p0[4], sm_p1[4];

    const int tid  = threadIdx.x;       // 0..127, one j per thread
    const int w    = tid >> 5;
    const int lane = tid & 31;

    const unsigned int M = g_M;
    const unsigned int sid = blockIdx.x;

    // ---- Trivial slabs: zero-fill column and exit ----
    if (sid >= M) {
        const unsigned int slab = g_trivial[sid - M];
        const int i  = slab & (S_DIM - 1);
        const int bb = slab >> 7;
        *reinterpret_cast<float2*>(
            out + ((size_t)(bb * S_DIM + tid) * S_DIM + i) * 2) =
            make_float2(0.0f, 0.0f);
        return;
    }

    const unsigned int slab = g_heavy[sid];
    const int i  = slab & (S_DIM - 1);
    const int bb = slab >> 7;
    const unsigned int* mask_w = reinterpret_cast<const unsigned int*>(mask_raw);
    const int okA = g_okA;

    // ---- Phase 0: per-j scalars + warp partials for T, Nv ----
    {
        const int j = tid;
        const size_t e = (size_t)(bb * S_DIM + j) * S_DIM + j;  // diagonal
        bool vb = okA ? (mask_raw[e] != 0) : (mask_w[e] != 0);
        float vf = vb ? 1.0f : 0.0f;
        sm_v[j] = vf;
        const float2 pe = *reinterpret_cast<const float2*>(
            s_edge + ((size_t)(bb * S_DIM + j) * S_DIM + i) * 2);
        sm_pe0[j] = pe.x;
        sm_pe1[j] = pe.y;
        float t = vf * (pe.y - pe.x);
        float n = vf;
        #pragma unroll
        for (int off = 16; off; off >>= 1) {
            t += __shfl_xor_sync(0xffffffffu, t, off);
            n += __shfl_xor_sync(0xffffffffu, n, off);
        }
        if (lane == 0) { sm_pT[w] = t; sm_pN[w] = n; }
    }
    __syncthreads();  // B1

    const float Nv = sm_pN[0] + sm_pN[1] + sm_pN[2] + sm_pN[3];
    const int   lv = (int)Nv;               // valid j are exactly 1..lv

    // ---- Phase 1: C[j] = sum_{k'} v_{k'} softplus(s_sib[b,j,i,k']) ----
    // Warp w owns rows j in [32w, 32w+32): 8 groups of 4 rows, double-buffered
    // so group g+1's loads are outstanding during group g's compute+reduce.
    {
        const float4 vk4 = reinterpret_cast<const float4*>(sm_v)[lane];
        const uint64_t vk01 = pk2(vk4.x, vk4.y);
        const uint64_t vk23 = pk2(vk4.z, vk4.w);
        const bool lane_ok = (4 * lane <= lv);
        const float* sbase = s_sib
            + (size_t)bb * (S_DIM * S_DIM * S_DIM) + (size_t)i * S_DIM;

        const bool b4 = (lane & 16) != 0;
        const bool b3 = (lane & 8)  != 0;

        auto load_group = [&](float4* buf, int g) {
            const int jbase = w * 32 + g * 4;
            #pragma unroll
            for (int r = 0; r < 4; r++) {
                buf[r] = make_float4(0.0f, 0.0f, 0.0f, 0.0f);
                if (sm_v[jbase + r] != 0.0f && lane_ok)
                    buf[r] = reinterpret_cast<const float4*>(
                        sbase + (size_t)(jbase + r) * (S_DIM * S_DIM))[lane];
            }
        };
        auto comp_group = [&](const float4* buf, int g) {
            const int jbase = w * 32 + g * 4;
            float p[4];
            #pragma unroll
            for (int r = 0; r < 4; r++) {
                float a = 0.0f;
                if (sm_v[jbase + r] != 0.0f) {       // warp-uniform branch
                    uint64_t acc = pk2(0.0f, 0.0f);
                    acc = sp2_acc(buf[r].x, buf[r].y, vk01, acc);
                    acc = sp2_acc(buf[r].z, buf[r].w, vk23, acc);
                    a = red2(acc);
                }
                p[r] = a;
            }
            // Folded reduction: 4 row-sums in 6 shuffles.
            float q[2];
            #pragma unroll
            for (int r = 0; r < 2; r++) {
                float mine  = b4 ? p[r + 2] : p[r];
                float other = b4 ? p[r]     : p[r + 2];
                q[r] = mine + __shfl_xor_sync(0xffffffffu, other, 16);
            }
            float mine  = b3 ? q[1] : q[0];
            float other = b3 ? q[0] : q[1];
            float s = mine + __shfl_xor_sync(0xffffffffu, other, 8);
            s += __shfl_xor_sync(0xffffffffu, s, 4);
            s += __shfl_xor_sync(0xffffffffu, s, 2);
            s += __shfl_xor_sync(0xffffffffu, s, 1);
            if ((lane & 7) == 0) {
                const int rho = (b3 ? 1 : 0) + (b4 ? 2 : 0);
                sm_C[jbase + rho] = s;
            }
        };

        float4 bufA[4], bufB[4];
        load_group(bufA, 0);
        #pragma unroll
        for (int g = 0; g < 8; g++) {
            if ((g & 1) == 0) {
                if (g < 7) load_group(bufB, g + 1);
                comp_group(bufA, g);
            } else {
                if (g < 7) load_group(bufA, g + 1);
                comp_group(bufB, g);
            }
        }
    }
    __syncthreads();  // B2

    // ---- Phase 2: d2[k] = v_k (T + C[k] - ln2*Nv); reduce S0, S1 ----
    {
        const float T  = sm_pT[0] + sm_pT[1] + sm_pT[2] + sm_pT[3];
        const float vj = sm_v[tid];
        const float d2 = vj * (T + sm_C[tid] - LN2F * Nv);
        float s0 = vj * softplus_poly(d2);
        float s1 = vj * d2;
        #pragma unroll
        for (int off = 16; off; off >>= 1) {
            s0 += __shfl_xor_sync(0xffffffffu, s0, off);
            s1 += __shfl_xor_sync(0xffffffffu, s1, off);
        }
        if (lane == 0) { sm_p0[w] = s0; sm_p1[w] = s1; }
    }
    __syncthreads();  // B3

    // ---- Phase 3: write marginals[b, j, i, :] ----
    {
        const float S0 = sm_p0[0] + sm_p0[1] + sm_p0[2] + sm_p0[3];
        const float S1 = sm_p1[0] + sm_p1[1] + sm_p1[2] + sm_p1[3];
        const float vj = sm_v[tid];
        float o0 = vj * (sm_pe0[tid] - S0);
        float o1 = vj * (sm_pe1[tid] + (S1 - S0));
        *reinterpret_cast<float2*>(
            out + ((size_t)(bb * S_DIM + tid) * S_DIM + i) * 2) =
            make_float2(o0, o1);
    }
}

extern "C" void kernel_launch(void* const* d_in, const int* in_sizes, int n_in,
                              void* d_out, int out_size) {
    // Remap by element counts: s_edge 262144, s_sib 16777216, mask 131072.
    const float* s_edge = nullptr;
    const float* s_sib  = nullptr;
    const unsigned char* mask = nullptr;
    for (int t = 0; t < n_in; t++) {
        if (in_sizes[t] == 262144)        s_edge = (const float*)d_in[t];
        else if (in_sizes[t] == 16777216) s_sib  = (const float*)d_in[t];
        else if (in_sizes[t] == 131072)   mask   = (const unsigned char*)d_in[t];
    }
    float* out = (float*)d_out;
    (void)out_size;

    schedule_kernel<<<1, NSLAB>>>(mask);
    lbp_kernel<<<NSLAB, 128>>>(s_edge, s_sib, mask, out);
}

// round 8
// speedup vs baseline: 1.1068x; 1.1068x over previous
#include <cuda_runtime.h>
#include <cstdint>

// LoopyBeliefPropagation: B=8, S=128, MAX_ITER=3
//
// Algebra (d = m1 - m0, m normalized over q): d2[j,k] = db2[k] - db1[k]
// (softplus(s_sib) cancels between iterations), so per (i,b) slab the only
// O(S^2) work is C[k] = sum_{k'} v_{k'} softplus(s_sib[b,k,i,k']) plus a
// scalar epilogue. softplus = EX2 + degree-6 poly in z=2e^{-|x|}-1, packed
// fma.rn.f32x2 (R6).
//
// R8: BRANCH-FREE phase 1. R3/R5/R6 all hit a 17us wall with per-SM delivered
// BW ~15 GB/s = ~40 lines in flight x 128B / 600cyc — the per-row
// `if (sm_v[j])` guards forced ptxas into BSSY/BSYNC per load group,
// serializing load issue and capping MLP. Now all 128 rows load
// unconditionally (straight-line 8x LDG.128 per group); masking is algebraic:
// vk kills invalid k' in the FMA, and phase 2's d2 = vj*(...) kills invalid-j
// garbage C[j]. Inputs are finite normals so no NaN/Inf risk.

#define S_DIM 128
#define LN2F 0.69314718055994530942f
#define NL2E 1.4426950408889634f   // log2(e)

// ---- packed f32x2 helpers ----
__device__ __forceinline__ uint64_t pk2(float lo, float hi) {
    uint64_t r;
    asm("mov.b64 %0, {%1, %2};" : "=l"(r) : "f"(lo), "f"(hi));
    return r;
}
__device__ __forceinline__ uint64_t fma2(uint64_t a, uint64_t b, uint64_t c) {
    uint64_t d;
    asm("fma.rn.f32x2 %0, %1, %2, %3;" : "=l"(d) : "l"(a), "l"(b), "l"(c));
    return d;
}
__device__ __forceinline__ uint64_t add2(uint64_t a, uint64_t b) {
    uint64_t d;
    asm("add.rn.f32x2 %0, %1, %2;" : "=l"(d) : "l"(a), "l"(b));
    return d;
}
__device__ __forceinline__ float red2(uint64_t a) {
    float lo, hi;
    asm("mov.b64 {%0, %1}, %2;" : "=f"(lo), "=f"(hi) : "l"(a));
    return lo + hi;
}
__device__ __forceinline__ float ex2f(float x) {
    float y;
    asm("ex2.approx.f32 %0, %1;" : "=f"(y) : "f"(x));
    return y;
}

// Polynomial coefficients for g(z) ~= log1p(e), z = 2e-1 in [-1,1]
#define PB0  0.40545900f
#define PB1  0.33334200f
#define PB2 -0.05556080f
#define PB3  0.01227890f
#define PB4 -0.00305808f
#define PB5  0.00095157f
#define PB6 -0.00027211f

// acc += vk2 * softplus2(x0, x1)   (packed)
__device__ __forceinline__ uint64_t sp2_acc(float x0, float x1,
                                            uint64_t vk2, uint64_t acc) {
    float e0 = ex2f(fmaf(fabsf(x0), -NL2E, 1.0f));   // 2*exp(-|x0|)
    float e1 = ex2f(fmaf(fabsf(x1), -NL2E, 1.0f));
    uint64_t z = add2(pk2(e0, e1), pk2(-1.0f, -1.0f));
    uint64_t g = pk2(PB6, PB6);
    g = fma2(g, z, pk2(PB5, PB5));
    g = fma2(g, z, pk2(PB4, PB4));
    g = fma2(g, z, pk2(PB3, PB3));
    g = fma2(g, z, pk2(PB2, PB2));
    g = fma2(g, z, pk2(PB1, PB1));
    g = fma2(g, z, pk2(PB0, PB0));
    uint64_t sp = add2(pk2(fmaxf(x0, 0.0f), fmaxf(x1, 0.0f)), g);
    return fma2(vk2, sp, acc);
}

__device__ __forceinline__ float softplus_poly(float x) {
    float z = ex2f(fmaf(fabsf(x), -NL2E, 1.0f)) - 1.0f;
    float g = PB6;
    g = fmaf(g, z, PB5);
    g = fmaf(g, z, PB4);
    g = fmaf(g, z, PB3);
    g = fmaf(g, z, PB2);
    g = fmaf(g, z, PB1);
    g = fmaf(g, z, PB0);
    return fmaxf(x, 0.0f) + g;
}

__global__ __launch_bounds__(128, 8)
void lbp_kernel(const float* __restrict__ s_edge,
                const float* __restrict__ s_sib,
                const unsigned char* __restrict__ mask_raw,
                float* __restrict__ out)
{
    __shared__ float sm_v[S_DIM];
    __shared__ float sm_pe0[S_DIM];
    __shared__ float sm_pe1[S_DIM];
    __shared__ float sm_C[S_DIM];
    __shared__ float sm_pT[4], sm_pN[4], sm_p0[4], sm_p1[4];

    const int slab = blockIdx.x;
    const int i   = slab & (S_DIM - 1);
    const int bb  = slab >> 7;
    const int tid  = threadIdx.x;       // 0..127, one j per thread
    const int w    = tid >> 5;
    const int lane = tid & 31;
    const unsigned int* mask_w = reinterpret_cast<const unsigned int*>(mask_raw);

    // ---- Mask element-width detection on batch-0 diagonal (v[0]=0, v[1]=1,
    // monotone non-increasing). R2 evidence: 4-byte elements; keep it robust.
    int predA = 1;
    {
        unsigned char vj  = mask_raw[tid * (S_DIM + 1)] != 0;
        unsigned char vj1 = (tid < S_DIM - 1)
                          ? (mask_raw[(tid + 1) * (S_DIM + 1)] != 0) : 0;
        if (tid == 0)              predA = (vj == 0);
        else if (tid == 1)         predA = (vj == 1) && (vj >= vj1);
        else if (tid < S_DIM - 1)  predA = (vj >= vj1);
    }
    const int okA = __syncthreads_and(predA);

    // ---- Phase 0: per-j scalars + warp partials for T, Nv ----
    {
        const int j = tid;
        const size_t e = (size_t)(bb * S_DIM + j) * S_DIM + j;  // diagonal
        bool vb = okA ? (mask_raw[e] != 0) : (mask_w[e] != 0);
        float vf = vb ? 1.0f : 0.0f;
        sm_v[j] = vf;
        const float2 pe = *reinterpret_cast<const float2*>(
            s_edge + ((size_t)(bb * S_DIM + j) * S_DIM + i) * 2);
        sm_pe0[j] = pe.x;
        sm_pe1[j] = pe.y;
        float t = vf * (pe.y - pe.x);
        float n = vf;
        #pragma unroll
        for (int off = 16; off; off >>= 1) {
            t += __shfl_xor_sync(0xffffffffu, t, off);
            n += __shfl_xor_sync(0xffffffffu, n, off);
        }
        if (lane == 0) { sm_pT[w] = t; sm_pN[w] = n; }
    }
    __syncthreads();  // B1

    // ---- Early out: invalid i -> slab output is all zeros ----
    if (sm_v[i] == 0.0f) {
        *reinterpret_cast<float2*>(
            out + ((size_t)(bb * S_DIM + tid) * S_DIM + i) * 2) =
            make_float2(0.0f, 0.0f);
        return;
    }

    const float Nv = sm_pN[0] + sm_pN[1] + sm_pN[2] + sm_pN[3];

    // ---- Phase 1: C[j] = sum_{k'} v_{k'} softplus(s_sib[b,j,i,k']) ----
    // Warp w owns rows j in [32w, 32w+32): 4 groups of 8 rows, NO branches.
    // Lane covers k' = 4*lane..4*lane+3 (one float4 = full row per warp).
    {
        const float4 vk4 = reinterpret_cast<const float4*>(sm_v)[lane];
        const uint64_t vk01 = pk2(vk4.x, vk4.y);
        const uint64_t vk23 = pk2(vk4.z, vk4.w);
        const float* sbase = s_sib
            + (size_t)bb * (S_DIM * S_DIM * S_DIM) + (size_t)i * S_DIM;

        const bool b4 = (lane & 16) != 0;
        const bool b3 = (lane & 8)  != 0;
        const bool b2 = (lane & 4)  != 0;

        #pragma unroll
        for (int g = 0; g < 4; g++) {
            const int jbase = w * 32 + g * 8;

            float4 rv[8];
            #pragma unroll
            for (int r = 0; r < 8; r++)
                rv[r] = reinterpret_cast<const float4*>(
                    sbase + (size_t)(jbase + r) * (S_DIM * S_DIM))[lane];

            float p[8];
            #pragma unroll
            for (int r = 0; r < 8; r++) {
                uint64_t acc = pk2(0.0f, 0.0f);
                acc = sp2_acc(rv[r].x, rv[r].y, vk01, acc);
                acc = sp2_acc(rv[r].z, rv[r].w, vk23, acc);
                p[r] = red2(acc);
            }

            // Folded reduction: 8 row-sums in 9 shuffles.
            float q[4];
            #pragma unroll
            for (int r = 0; r < 4; r++) {
                float mine  = b4 ? p[r + 4] : p[r];
                float other = b4 ? p[r]     : p[r + 4];
                q[r] = mine + __shfl_xor_sync(0xffffffffu, other, 16);
            }
            float u[2];
            #pragma unroll
            for (int r = 0; r < 2; r++) {
                float mine  = b3 ? q[r + 2] : q[r];
                float other = b3 ? q[r]     : q[r + 2];
                u[r] = mine + __shfl_xor_sync(0xffffffffu, other, 8);
            }
            float mine  = b2 ? u[1] : u[0];
            float other = b2 ? u[0] : u[1];
            float s = mine + __shfl_xor_sync(0xffffffffu, other, 4);
            s += __shfl_xor_sync(0xffffffffu, s, 2);
            s += __shfl_xor_sync(0xffffffffu, s, 1);
            if ((lane & 3) == 0) {
                const int rho = (b2 ? 1 : 0) + (b3 ? 2 : 0) + (b4 ? 4 : 0);
                sm_C[jbase + rho] = s;
            }
        }
    }
    __syncthreads();  // B2

    // ---- Phase 2: d2[k] = v_k (T + C[k] - ln2*Nv); reduce S0, S1 ----
    // vj multiplies C here, so garbage C[j] from invalid rows is annihilated.
    {
        const float T  = sm_pT[0] + sm_pT[1] + sm_pT[2] + sm_pT[3];
        const float vj = sm_v[tid];
        const float d2 = vj * (T + sm_C[tid] - LN2F * Nv);
        float s0 = vj * softplus_poly(d2);
        float s1 = vj * d2;
        #pragma unroll
        for (int off = 16; off; off >>= 1) {
            s0 += __shfl_xor_sync(0xffffffffu, s0, off);
            s1 += __shfl_xor_sync(0xffffffffu, s1, off);
        }
        if (lane == 0) { sm_p0[w] = s0; sm_p1[w] = s1; }
    }
    __syncthreads();  // B3

    // ---- Phase 3: write marginals[b, j, i, :] ----
    {
        const float S0 = sm_p0[0] + sm_p0[1] + sm_p0[2] + sm_p0[3];
        const float S1 = sm_p1[0] + sm_p1[1] + sm_p1[2] + sm_p1[3];
        const float vj = sm_v[tid];
        float o0 = vj * (sm_pe0[tid] - S0);
        float o1 = vj * (sm_pe1[tid] + (S1 - S0));
        *reinterpret_cast<float2*>(
            out + ((size_t)(bb * S_DIM + tid) * S_DIM + i) * 2) =
            make_float2(o0, o1);
    }
}

extern "C" void kernel_launch(void* const* d_in, const int* in_sizes, int n_in,
                              void* d_out, int out_size) {
    // Remap by element counts: s_edge 262144, s_sib 16777216, mask 131072.
    const float* s_edge = nullptr;
    const float* s_sib  = nullptr;
    const unsigned char* mask = nullptr;
    for (int t = 0; t < n_in; t++) {
        if (in_sizes[t] == 262144)        s_edge = (const float*)d_in[t];
        else if (in_sizes[t] == 16777216) s_sib  = (const float*)d_in[t];
        else if (in_sizes[t] == 131072)   mask   = (const unsigned char*)d_in[t];
    }
    float* out = (float*)d_out;
    (void)out_size;

    lbp_kernel<<<8 * S_DIM, 128>>>(s_edge, s_sib, mask, out);
}